// round 3
// baseline (speedup 1.0000x reference)
#include <cuda_runtime.h>
#include <cuda_fp8.h>
#include <cuda_fp16.h>

#define T_ 512
#define D_ 2048
#define I_ 768
#define E_ 16
#define K_ 8
#define H2_ 1536   // 2*I

// ---------------- scratch (device globals; no allocations allowed) ----------
__device__ __half g_xqh[T_ * D_];          // 2 MB   quant-dequant activations (fp16, exact)
__device__ int    g_tok[E_ * T_];          // token index per (expert, slot)
__device__ float  g_wt[E_ * T_];           // combined routing weight per slot
__device__ int    g_cnt[E_];               // tokens per expert
__device__ int    g_slot[T_ * E_];         // (token, expert) -> slot or -1
__device__ __half g_acth[E_ * T_ * I_];    // 12.6MB silu(gate)*up (fp16)
__device__ float  g_y[E_ * T_ * D_];       // 64 MB  per-expert weighted outputs

// fp4 e2m1 nibble -> float (used only to build the smem LUT)
__device__ __forceinline__ float fp4f(unsigned nib) {
    unsigned e = (nib >> 1) & 3u, m = nib & 1u, s = (nib & 8u) << 28;
    unsigned bits = e ? (((e + 126u) << 23) | (m << 22)) : (m ? 0x3F000000u : 0u);
    return __uint_as_float(bits | s);
}

__device__ __forceinline__ void mma16816(float* c, const unsigned* a, const unsigned* b) {
    asm volatile(
        "mma.sync.aligned.m16n8k16.row.col.f32.f16.f16.f32 "
        "{%0,%1,%2,%3}, {%4,%5,%6,%7}, {%8,%9}, {%0,%1,%2,%3};\n"
        : "+f"(c[0]), "+f"(c[1]), "+f"(c[2]), "+f"(c[3])
        : "r"(a[0]), "r"(a[1]), "r"(a[2]), "r"(a[3]), "r"(b[0]), "r"(b[1]));
}

__device__ __forceinline__ void ldsm_x4(unsigned& r0, unsigned& r1, unsigned& r2,
                                        unsigned& r3, unsigned saddr) {
    asm volatile("ldmatrix.sync.aligned.m8n8.x4.shared.b16 {%0,%1,%2,%3}, [%4];\n"
                 : "=r"(r0), "=r"(r1), "=r"(r2), "=r"(r3) : "r"(saddr));
}

// ---------------- 1) fp8 quant-dequant (group = 32, one warp per group) -----
__global__ __launch_bounds__(256) void k_quant(const float* __restrict__ x) {
    int g    = blockIdx.x * 8 + (threadIdx.x >> 5);
    int lane = threadIdx.x & 31;
    int idx  = g * 32 + lane;
    float v  = x[idx];
    float a  = fabsf(v);
#pragma unroll
    for (int s = 16; s; s >>= 1) a = fmaxf(a, __shfl_xor_sync(0xffffffffu, a, s));
    a = fmaxf(a, 1e-4f);
    float scale   = __fdiv_rn(a, 448.0f);
    unsigned bits = __float_as_uint(scale);
    unsigned ex   = ((bits >> 23) & 255u) + ((bits & 0x7fffffu) ? 1u : 0u);
    ex = ex < 1u ? 1u : (ex > 254u ? 254u : ex);
    float rscale = __uint_as_float(ex << 23);
    float rinv   = __uint_as_float((254u - ex) << 23);
    float q      = v * rinv;
    __nv_fp8_storage_t f8 = __nv_cvt_float_to_fp8(q, __NV_SATFINITE, __NV_E4M3);
    __half_raw hr = __nv_cvt_fp8_to_halfraw(f8, __NV_E4M3);
    g_xqh[idx] = __float2half(__half2float(__half(hr)) * rscale);
}

// ---------------- 2) routing compaction (single block, deterministic) -------
__global__ __launch_bounds__(512) void k_route(const float* __restrict__ tw,
                                               const int* __restrict__ tids) {
    __shared__ int s_cnt[E_];
    int t = threadIdx.x;
    if (t < E_) s_cnt[t] = 0;
    __syncthreads();
    float w[K_]; int id[K_];
#pragma unroll
    for (int k = 0; k < K_; k++) { w[k] = tw[t * K_ + k]; id[k] = tids[t * K_ + k]; }
    for (int e = 0; e < E_; e++) {
        float c = 0.f;
#pragma unroll
        for (int k = 0; k < K_; k++) if (id[k] == e) c += w[k];
        int slot = -1;
        if (c > 0.f) {
            slot = atomicAdd(&s_cnt[e], 1);
            g_tok[e * T_ + slot] = t;
            g_wt[e * T_ + slot]  = c;
        }
        g_slot[t * E_ + e] = slot;
    }
    __syncthreads();
    if (t < E_) g_cnt[t] = s_cnt[t];
}

// ---------------- 3) GEMM1 fused silu: 128M x (64g+64u interleaved) x BK32 --
__global__ __launch_bounds__(256, 2) void k_gemm1(const int* __restrict__ w13,
                                                  const int* __restrict__ w13s) {
    const int e   = blockIdx.z;
    const int cnt = g_cnt[e];
    const int m0  = blockIdx.y * 128;
    if (m0 >= cnt) return;
    const int n0  = blockIdx.x * 64;   // gate-feature base

    __shared__ __half  as_[2][128][40];
    __shared__ __half  ws [2][128][40];
    __shared__ __half2 lut[256];
    __shared__ int     toks[128];

    const int tid  = threadIdx.x;
    const int lane = tid & 31;
    const int w    = tid >> 5;

    lut[tid] = __floats2half2_rn(fp4f(tid & 15u), fp4f((tid >> 4) & 15u));
    if (tid < 128) {
        int m = m0 + tid;
        toks[tid] = (m < cnt) ? g_tok[e * T_ + m] : -1;
    }
    __syncthreads();

    // fill mappings
    const int ar  = tid >> 1;
    const int acx = (tid & 1) * 16;
    const int tok = toks[ar];
    const __half* aG = g_xqh + (tok < 0 ? 0 : tok) * D_;

    const int wr = tid >> 1;
    const int wb = (tid & 1) * 8;
    const int f  = (wr & 1) ? (I_ + n0 + (wr >> 1)) : (n0 + (wr >> 1));
    const int* wp0 = w13  + (e * H2_ + f) * (D_ / 2);
    const int* sp0 = w13s + (e * H2_ + f) * (D_ / 32);

    // warp tile: 4m x 2n
    const int mw  = (w >> 1) * 32;
    const int nwc = (w & 1) * 64;
    const int rowoff = (lane & 7) + ((lane >> 3) & 1) * 8;
    const int coloff = (lane >> 4) * 8;

    float acc[2][8][4] = {};
    uint4 av0, av1;
    int4  qv0, qv1;
    float sc;

    auto LOAD = [&](int kt) {
        int k0 = kt * 32;
        if (tok >= 0) {
            av0 = *(const uint4*)(aG + k0 + acx);
            av1 = *(const uint4*)(aG + k0 + acx + 8);
        } else {
            av0 = make_uint4(0, 0, 0, 0);
            av1 = make_uint4(0, 0, 0, 0);
        }
        qv0 = *(const int4*)(wp0 + (k0 >> 1) + wb);
        qv1 = *(const int4*)(wp0 + (k0 >> 1) + wb + 4);
        sc  = __uint_as_float(((unsigned)sp0[k0 >> 5]) << 23);
    };
    auto STS = [&](int st) {
        *(uint4*)&as_[st][ar][acx]     = av0;
        *(uint4*)&as_[st][ar][acx + 8] = av1;
        __half2 hs = __float2half2_rn(sc);
        int q[8] = {qv0.x, qv0.y, qv0.z, qv0.w, qv1.x, qv1.y, qv1.z, qv1.w};
#pragma unroll
        for (int j = 0; j < 8; j++)
            *(__half2*)&ws[st][wr][(wb + j) * 2] = __hmul2(lut[q[j] & 255], hs);
    };
    auto MMA = [&](int st) {
        unsigned abase = (unsigned)__cvta_generic_to_shared(&as_[st][0][0]);
        unsigned bbase = (unsigned)__cvta_generic_to_shared(&ws[st][0][0]);
#pragma unroll
        for (int ks = 0; ks < 2; ks++) {
            int kc = ks * 16 + coloff;
            unsigned a[2][4], b[4][4];
#pragma unroll
            for (int mi = 0; mi < 2; mi++)
                ldsm_x4(a[mi][0], a[mi][1], a[mi][2], a[mi][3],
                        abase + ((mw + mi * 16 + rowoff) * 40 + kc) * 2);
#pragma unroll
            for (int p = 0; p < 4; p++)
                ldsm_x4(b[p][0], b[p][1], b[p][2], b[p][3],
                        bbase + ((nwc + p * 16 + rowoff) * 40 + kc) * 2);
#pragma unroll
            for (int mi = 0; mi < 2; mi++)
#pragma unroll
                for (int p = 0; p < 4; p++) {
                    unsigned bf0[2] = {b[p][0], b[p][2]};
                    unsigned bf1[2] = {b[p][1], b[p][3]};
                    mma16816(acc[mi][p * 2],     a[mi], bf0);
                    mma16816(acc[mi][p * 2 + 1], a[mi], bf1);
                }
        }
    };

    const int KT = D_ / 32;
    LOAD(0);
    STS(0);
#pragma unroll 1
    for (int kt = 0; kt < KT; kt++) {
        __syncthreads();
        bool more = (kt + 1 < KT);
        if (more) LOAD(kt + 1);
        MMA(kt & 1);
        if (more) STS((kt + 1) & 1);
    }

    // epilogue: acc pairs (even,odd) = (gate_j, up_j); silu in-register
    const int jbase = nwc >> 1;
#pragma unroll
    for (int mi = 0; mi < 2; mi++)
#pragma unroll
        for (int p = 0; p < 8; p++) {
            int r   = mw + mi * 16 + (lane >> 2);
            int j   = n0 + jbase + p * 4 + (lane & 3);
            int row = m0 + r;
            if (row < cnt) {
                float g = acc[mi][p][0], u = acc[mi][p][1];
                g_acth[(e * T_ + row) * I_ + j] =
                    __float2half(g / (1.f + expf(-g)) * u);
            }
            if (row + 8 < cnt) {
                float g = acc[mi][p][2], u = acc[mi][p][3];
                g_acth[(e * T_ + row + 8) * I_ + j] =
                    __float2half(g / (1.f + expf(-g)) * u);
            }
        }
}

// ---------------- 4) GEMM2: y = a @ w2^T (128M x 128N x BK32) ---------------
__global__ __launch_bounds__(256, 2) void k_gemm2(const int* __restrict__ w2,
                                                  const int* __restrict__ w2s) {
    const int e   = blockIdx.z;
    const int cnt = g_cnt[e];
    const int m0  = blockIdx.y * 128;
    if (m0 >= cnt) return;
    const int n0  = blockIdx.x * 128;

    __shared__ __half  as_[2][128][40];
    __shared__ __half  ws [2][128][40];
    __shared__ __half2 lut[256];

    const int tid  = threadIdx.x;
    const int lane = tid & 31;
    const int w    = tid >> 5;

    lut[tid] = __floats2half2_rn(fp4f(tid & 15u), fp4f((tid >> 4) & 15u));
    __syncthreads();

    const int ar  = tid >> 1;
    const int acx = (tid & 1) * 16;
    const int arow_ok = (m0 + ar) < cnt;
    const __half* aG = g_acth + (e * T_ + (arow_ok ? m0 + ar : 0)) * I_;

    const int wr = tid >> 1;
    const int wb = (tid & 1) * 8;
    const int f  = n0 + wr;
    const int* wp0 = w2  + (e * D_ + f) * (I_ / 2);
    const int* sp0 = w2s + (e * D_ + f) * (I_ / 32);

    const int mw  = (w >> 1) * 32;
    const int nwc = (w & 1) * 64;
    const int rowoff = (lane & 7) + ((lane >> 3) & 1) * 8;
    const int coloff = (lane >> 4) * 8;

    float acc[2][8][4] = {};
    uint4 av0, av1;
    int4  qv0, qv1;
    float sc;

    auto LOAD = [&](int kt) {
        int k0 = kt * 32;
        if (arow_ok) {
            av0 = *(const uint4*)(aG + k0 + acx);
            av1 = *(const uint4*)(aG + k0 + acx + 8);
        } else {
            av0 = make_uint4(0, 0, 0, 0);
            av1 = make_uint4(0, 0, 0, 0);
        }
        qv0 = *(const int4*)(wp0 + (k0 >> 1) + wb);
        qv1 = *(const int4*)(wp0 + (k0 >> 1) + wb + 4);
        sc  = __uint_as_float(((unsigned)sp0[k0 >> 5]) << 23);
    };
    auto STS = [&](int st) {
        *(uint4*)&as_[st][ar][acx]     = av0;
        *(uint4*)&as_[st][ar][acx + 8] = av1;
        __half2 hs = __float2half2_rn(sc);
        int q[8] = {qv0.x, qv0.y, qv0.z, qv0.w, qv1.x, qv1.y, qv1.z, qv1.w};
#pragma unroll
        for (int j = 0; j < 8; j++)
            *(__half2*)&ws[st][wr][(wb + j) * 2] = __hmul2(lut[q[j] & 255], hs);
    };
    auto MMA = [&](int st) {
        unsigned abase = (unsigned)__cvta_generic_to_shared(&as_[st][0][0]);
        unsigned bbase = (unsigned)__cvta_generic_to_shared(&ws[st][0][0]);
#pragma unroll
        for (int ks = 0; ks < 2; ks++) {
            int kc = ks * 16 + coloff;
            unsigned a[2][4], b[4][4];
#pragma unroll
            for (int mi = 0; mi < 2; mi++)
                ldsm_x4(a[mi][0], a[mi][1], a[mi][2], a[mi][3],
                        abase + ((mw + mi * 16 + rowoff) * 40 + kc) * 2);
#pragma unroll
            for (int p = 0; p < 4; p++)
                ldsm_x4(b[p][0], b[p][1], b[p][2], b[p][3],
                        bbase + ((nwc + p * 16 + rowoff) * 40 + kc) * 2);
#pragma unroll
            for (int mi = 0; mi < 2; mi++)
#pragma unroll
                for (int p = 0; p < 4; p++) {
                    unsigned bf0[2] = {b[p][0], b[p][2]};
                    unsigned bf1[2] = {b[p][1], b[p][3]};
                    mma16816(acc[mi][p * 2],     a[mi], bf0);
                    mma16816(acc[mi][p * 2 + 1], a[mi], bf1);
                }
        }
    };

    const int KT = I_ / 32;
    LOAD(0);
    STS(0);
#pragma unroll 1
    for (int kt = 0; kt < KT; kt++) {
        __syncthreads();
        bool more = (kt + 1 < KT);
        if (more) LOAD(kt + 1);
        MMA(kt & 1);
        if (more) STS((kt + 1) & 1);
    }

    // epilogue: scale by routing weight, write y (float2 per acc pair)
#pragma unroll
    for (int mi = 0; mi < 2; mi++)
#pragma unroll
        for (int p = 0; p < 8; p++) {
            int r   = mw + mi * 16 + (lane >> 2);
            int col = n0 + nwc + p * 8 + (lane & 3) * 2;
            int row = m0 + r;
            if (row < cnt) {
                float wc = g_wt[e * T_ + row];
                *(float2*)&g_y[(e * T_ + row) * D_ + col] =
                    make_float2(acc[mi][p][0] * wc, acc[mi][p][1] * wc);
            }
            if (row + 8 < cnt) {
                float wc = g_wt[e * T_ + row + 8];
                *(float2*)&g_y[(e * T_ + row + 8) * D_ + col] =
                    make_float2(acc[mi][p][2] * wc, acc[mi][p][3] * wc);
            }
        }
}

// ---------------- 5) combine: out[t,d] = sum_e y[e, slot(t,e), d] -----------
__global__ __launch_bounds__(256) void k_combine(float* __restrict__ out) {
    int t = blockIdx.x;
    __shared__ int sl[E_];
    if (threadIdx.x < E_) sl[threadIdx.x] = g_slot[t * E_ + threadIdx.x];
    __syncthreads();
    for (int d = threadIdx.x; d < D_; d += 256) {
        float acc = 0.f;
#pragma unroll
        for (int e = 0; e < E_; e++) {
            int s = sl[e];
            if (s >= 0) acc += g_y[(e * T_ + s) * D_ + d];
        }
        out[t * D_ + d] = acc;
    }
}

// ---------------- launch -----------------------------------------------------
extern "C" void kernel_launch(void* const* d_in, const int* in_sizes, int n_in,
                              void* d_out, int out_size) {
    const float* x    = (const float*)d_in[0];
    const float* tw   = (const float*)d_in[1];
    const int*   tids = (const int*)d_in[2];
    const int*   w13  = (const int*)d_in[3];
    const int*   w13s = (const int*)d_in[4];
    const int*   w2   = (const int*)d_in[5];
    const int*   w2s  = (const int*)d_in[6];
    float* out = (float*)d_out;

    k_quant<<<(T_ * D_ / 32) / 8, 256>>>(x);
    k_route<<<1, 512>>>(tw, tids);
    k_gemm1<<<dim3(I_ / 64, T_ / 128, E_), 256>>>(w13, w13s);
    k_gemm2<<<dim3(D_ / 128, T_ / 128, E_), 256>>>(w2, w2s);
    k_combine<<<T_, 256>>>(out);
}

// round 8
// speedup vs baseline: 1.5085x; 1.5085x over previous
#include <cuda_runtime.h>
#include <cuda_fp8.h>
#include <cuda_fp16.h>
#include <cstdint>

#define T_ 512
#define D_ 2048
#define I_ 768
#define E_ 16
#define K_ 8
#define H2_ 1536   // 2*I

// ---------------- scratch (device globals; no allocations allowed) ----------
__device__ uint8_t g_xq8[T_ * D_];           // e4m3 quantized activations
__device__ float   g_xsc[T_ * (D_ / 32)];    // per-group activation scales
__device__ int     g_tok[E_ * T_];
__device__ float   g_wt[E_ * T_];
__device__ int     g_cnt[E_];
__device__ int     g_slot[T_ * E_];
__device__ __half  g_acth[E_ * T_ * I_];     // silu(gate)*up (fp16)
__device__ float   g_y[E_ * T_ * D_];

// ---------------- helpers ----------------------------------------------------
__device__ __forceinline__ uint32_t s2u(const void* p) {
    uint32_t a;
    asm("{ .reg .u64 t; cvta.to.shared.u64 t, %1; cvt.u32.u64 %0, t; }" : "=r"(a) : "l"(p));
    return a;
}
__device__ __forceinline__ float fp4f(unsigned nib) {
    unsigned e = (nib >> 1) & 3u, m = nib & 1u, s = (nib & 8u) << 28;
    unsigned bits = e ? (((e + 126u) << 23) | (m << 22)) : (m ? 0x3F000000u : 0u);
    return __uint_as_float(bits | s);
}
__device__ __forceinline__ void cpa16(uint32_t d, const void* s) {
    asm volatile("cp.async.cg.shared.global [%0], [%1], 16;" :: "r"(d), "l"(s));
}
__device__ __forceinline__ void cpa4(uint32_t d, const void* s) {
    asm volatile("cp.async.ca.shared.global [%0], [%1], 4;" :: "r"(d), "l"(s));
}
#define CP_COMMIT() asm volatile("cp.async.commit_group;" ::: "memory")
#define CP_WAIT0()  asm volatile("cp.async.wait_group 0;" ::: "memory")

__device__ __forceinline__ void mma_f16(float* c, const unsigned* a, const unsigned* b) {
    asm volatile(
        "mma.sync.aligned.m16n8k16.row.col.f32.f16.f16.f32 "
        "{%0,%1,%2,%3}, {%4,%5,%6,%7}, {%8,%9}, {%0,%1,%2,%3};\n"
        : "+f"(c[0]), "+f"(c[1]), "+f"(c[2]), "+f"(c[3])
        : "r"(a[0]), "r"(a[1]), "r"(a[2]), "r"(a[3]), "r"(b[0]), "r"(b[1]));
}
__device__ __forceinline__ void mma_fp8(float* d, const unsigned* a, const unsigned* b) {
    asm volatile(
        "mma.sync.aligned.m16n8k32.row.col.f32.e4m3.e4m3.f32 "
        "{%0,%1,%2,%3}, {%4,%5,%6,%7}, {%8,%9}, {%10,%11,%12,%13};\n"
        : "=f"(d[0]), "=f"(d[1]), "=f"(d[2]), "=f"(d[3])
        : "r"(a[0]), "r"(a[1]), "r"(a[2]), "r"(a[3]), "r"(b[0]), "r"(b[1]),
          "f"(0.f), "f"(0.f), "f"(0.f), "f"(0.f));
}
__device__ __forceinline__ void ldsm_x4(unsigned& r0, unsigned& r1, unsigned& r2,
                                        unsigned& r3, uint32_t saddr) {
    asm volatile("ldmatrix.sync.aligned.m8n8.x4.shared.b16 {%0,%1,%2,%3}, [%4];\n"
                 : "=r"(r0), "=r"(r1), "=r"(r2), "=r"(r3) : "r"(saddr));
}

// ---------------- 1) fp8 quant: store e4m3 bytes + group scales --------------
__global__ __launch_bounds__(256) void k_quant(const float* __restrict__ x) {
    int g    = blockIdx.x * 8 + (threadIdx.x >> 5);
    int lane = threadIdx.x & 31;
    int idx  = g * 32 + lane;
    float v  = x[idx];
    float a  = fabsf(v);
#pragma unroll
    for (int s = 16; s; s >>= 1) a = fmaxf(a, __shfl_xor_sync(0xffffffffu, a, s));
    a = fmaxf(a, 1e-4f);
    float scale   = __fdiv_rn(a, 448.0f);
    unsigned bits = __float_as_uint(scale);
    unsigned ex   = ((bits >> 23) & 255u) + ((bits & 0x7fffffu) ? 1u : 0u);
    ex = ex < 1u ? 1u : (ex > 254u ? 254u : ex);
    float rscale = __uint_as_float(ex << 23);
    float rinv   = __uint_as_float((254u - ex) << 23);
    g_xq8[idx] = (uint8_t)__nv_cvt_float_to_fp8(v * rinv, __NV_SATFINITE, __NV_E4M3);
    if (lane == 0) g_xsc[g] = rscale;
}

// ---------------- 2) routing compaction --------------------------------------
__global__ __launch_bounds__(512) void k_route(const float* __restrict__ tw,
                                               const int* __restrict__ tids) {
    __shared__ int s_cnt[E_];
    int t = threadIdx.x;
    if (t < E_) s_cnt[t] = 0;
    __syncthreads();
    float w[K_]; int id[K_];
#pragma unroll
    for (int k = 0; k < K_; k++) { w[k] = tw[t * K_ + k]; id[k] = tids[t * K_ + k]; }
    for (int e = 0; e < E_; e++) {
        float c = 0.f;
#pragma unroll
        for (int k = 0; k < K_; k++) if (id[k] == e) c += w[k];
        int slot = -1;
        if (c > 0.f) {
            slot = atomicAdd(&s_cnt[e], 1);
            g_tok[e * T_ + slot] = t;
            g_wt[e * T_ + slot]  = c;
        }
        g_slot[t * E_ + e] = slot;
    }
    __syncthreads();
    if (t < E_) g_cnt[t] = s_cnt[t];
}

// ---------------- 3) GEMM1: fp8 QMMA, 128M x 64N(32g+32u interleaved), BK32 --
__global__ __launch_bounds__(256, 3) void k_gemm1(const int* __restrict__ w13,
                                                  const int* __restrict__ w13s) {
    const int e   = blockIdx.z;
    const int cnt = g_cnt[e];
    const int m0  = blockIdx.y * 128;
    if (m0 >= cnt) return;
    const int n0g = blockIdx.x * 32;   // gate-feature base (tile covers 32g+32u)

    __shared__ __align__(16) uint8_t sA[2][128 * 48];  // fp8, 32B data + 16B pad
    __shared__ __align__(16) uint8_t sB[2][64 * 48];
    __shared__ __align__(16) int     sPk[2][1024];     // staged packed weights
    __shared__ int     sScv[2][256];                   // per-thread dup B scale
    __shared__ float   sSa[2][128];                    // A scales per row
    __shared__ __half2 lut[256];
    __shared__ int     toks[128];

    const int tid = threadIdx.x, wid = tid >> 5, lane = tid & 31;
    lut[tid] = __floats2half2_rn(fp4f(tid & 15u), fp4f((tid >> 4) & 15u));
    if (tid < 128) {
        int m = m0 + tid;
        toks[tid] = (m < cnt) ? g_tok[e * T_ + m] : g_tok[e * T_];
    }
    __syncthreads();

    // fill mappings
    const int car = tid >> 1, cah = (tid & 1) * 16;
    const uint8_t* aG = g_xq8 + toks[car] * D_;
    const int wr = tid >> 2, q = tid & 3;
    const int f  = (wr & 1) ? (I_ + n0g + (wr >> 1)) : (n0g + (wr >> 1));
    const int* wp  = w13  + (e * H2_ + f) * (D_ / 2);
    const int* scp = w13s + (e * H2_ + f) * (D_ / 32);
    const float* xscp = (tid < 128) ? (g_xsc + toks[tid] * (D_ / 32)) : g_xsc;

    uint32_t uA[2]  = {s2u(&sA[0][0]),  s2u(&sA[1][0])};
    uint32_t uB[2]  = {s2u(&sB[0][0]),  s2u(&sB[1][0])};
    uint32_t uPk[2] = {s2u(&sPk[0][0]), s2u(&sPk[1][0])};
    uint32_t uSc[2] = {s2u(&sScv[0][0]), s2u(&sScv[1][0])};
    uint32_t uSa[2] = {s2u(&sSa[0][0]), s2u(&sSa[1][0])};

    const int mw = (wid >> 1) * 32, nw = (wid & 1) * 32;
    const int rowoff = (lane & 7) + ((lane >> 3) & 1) * 8;
    const int col16  = (lane >> 4) * 16;
    float acc[2][4][4] = {};

    auto CPL = [&](int kt, int s) {
        int k0 = kt * 32;
        cpa16(uA[s] + car * 48 + cah, aG + k0 + cah);
        cpa16(uPk[s] + (tid << 4), wp + (k0 >> 1) + q * 4);
        cpa4(uSc[s] + (tid << 2), scp + kt);
        if (tid < 128) cpa4(uSa[s] + (tid << 2), xscp + kt);
        CP_COMMIT();
    };
    auto DEQ = [&](int s) {
        int4 pk = *(const int4*)&sPk[s][tid << 2];
        unsigned sv = (unsigned)sScv[s][tid];
        __half2 hs = __float2half2_rn(__uint_as_float(sv << 23));
        __half2 h0 = __hmul2(lut[pk.x & 255], hs);
        __half2 h1 = __hmul2(lut[pk.y & 255], hs);
        __half2 h2 = __hmul2(lut[pk.z & 255], hs);
        __half2 h3 = __hmul2(lut[pk.w & 255], hs);
        unsigned p0 = __nv_cvt_halfraw2_to_fp8x2(*(__half2_raw*)&h0, __NV_SATFINITE, __NV_E4M3);
        unsigned p1 = __nv_cvt_halfraw2_to_fp8x2(*(__half2_raw*)&h1, __NV_SATFINITE, __NV_E4M3);
        unsigned p2 = __nv_cvt_halfraw2_to_fp8x2(*(__half2_raw*)&h2, __NV_SATFINITE, __NV_E4M3);
        unsigned p3 = __nv_cvt_halfraw2_to_fp8x2(*(__half2_raw*)&h3, __NV_SATFINITE, __NV_E4M3);
        *(uint2*)&sB[s][wr * 48 + q * 8] = make_uint2(p0 | (p1 << 16), p2 | (p3 << 16));
    };
    auto MMA = [&](int s) {
        unsigned a[2][4], b[2][4];
#pragma unroll
        for (int mi = 0; mi < 2; mi++)
            ldsm_x4(a[mi][0], a[mi][1], a[mi][2], a[mi][3],
                    uA[s] + (mw + mi * 16 + rowoff) * 48 + col16);
#pragma unroll
        for (int p = 0; p < 2; p++)
            ldsm_x4(b[p][0], b[p][1], b[p][2], b[p][3],
                    uB[s] + (nw + p * 16 + rowoff) * 48 + col16);
        float sa[2][2];
#pragma unroll
        for (int mi = 0; mi < 2; mi++) {
            sa[mi][0] = sSa[s][mw + mi * 16 + (lane >> 2)];
            sa[mi][1] = sSa[s][mw + mi * 16 + (lane >> 2) + 8];
        }
#pragma unroll
        for (int mi = 0; mi < 2; mi++)
#pragma unroll
            for (int nj = 0; nj < 4; nj++) {
                unsigned bf[2] = {b[nj >> 1][nj & 1], b[nj >> 1][(nj & 1) + 2]};
                float d[4];
                mma_fp8(d, a[mi], bf);
                acc[mi][nj][0] = fmaf(d[0], sa[mi][0], acc[mi][nj][0]);
                acc[mi][nj][1] = fmaf(d[1], sa[mi][0], acc[mi][nj][1]);
                acc[mi][nj][2] = fmaf(d[2], sa[mi][1], acc[mi][nj][2]);
                acc[mi][nj][3] = fmaf(d[3], sa[mi][1], acc[mi][nj][3]);
            }
    };

    const int KT = D_ / 32;
    CPL(0, 0);
#pragma unroll 1
    for (int kt = 0; kt < KT; kt++) {
        int s = kt & 1;
        CP_WAIT0();
        DEQ(s);
        __syncthreads();
        if (kt + 1 < KT) CPL(kt + 1, s ^ 1);
        MMA(s);
    }

    // epilogue: cols pair (even,odd) = (gate_j, up_j); silu in-register
#pragma unroll
    for (int mi = 0; mi < 2; mi++) {
        int r = mw + mi * 16 + (lane >> 2);
#pragma unroll
        for (int nj = 0; nj < 4; nj++) {
            int j   = n0g + ((nw + nj * 8) >> 1) + (lane & 3);
            int row = m0 + r;
            if (row < cnt) {
                float g = acc[mi][nj][0], u = acc[mi][nj][1];
                g_acth[(e * T_ + row) * I_ + j] = __float2half(g / (1.f + expf(-g)) * u);
            }
            if (row + 8 < cnt) {
                float g = acc[mi][nj][2], u = acc[mi][nj][3];
                g_acth[(e * T_ + row + 8) * I_ + j] = __float2half(g / (1.f + expf(-g)) * u);
            }
        }
    }
}

// ---------------- 4) GEMM2: fp16 HMMA, 128M x 64N, BK32 ---------------------
__global__ __launch_bounds__(256, 3) void k_gemm2(const int* __restrict__ w2,
                                                  const int* __restrict__ w2s) {
    const int e   = blockIdx.z;
    const int cnt = g_cnt[e];
    const int m0  = blockIdx.y * 128;
    if (m0 >= cnt) return;
    const int n0  = blockIdx.x * 64;

    __shared__ __align__(16) uint8_t sA[2][128 * 80];  // fp16, 64B data + 16B pad
    __shared__ __align__(16) uint8_t sB[2][64 * 80];
    __shared__ __align__(16) int     sPk[2][1024];
    __shared__ int     sScv[2][256];
    __shared__ __half2 lut[256];

    const int tid = threadIdx.x, wid = tid >> 5, lane = tid & 31;
    lut[tid] = __floats2half2_rn(fp4f(tid & 15u), fp4f((tid >> 4) & 15u));
    __syncthreads();

    const int car = tid >> 1, cab = (tid & 1) * 32;
    const int am  = (m0 + car < cnt) ? (m0 + car) : (cnt - 1);
    const __half* aG = g_acth + (e * T_ + am) * I_;
    const int wr = tid >> 2, q = tid & 3;
    const int f  = n0 + wr;
    const int* wp  = w2  + (e * D_ + f) * (I_ / 2);
    const int* scp = w2s + (e * D_ + f) * (I_ / 32);

    uint32_t uA[2]  = {s2u(&sA[0][0]),  s2u(&sA[1][0])};
    uint32_t uB[2]  = {s2u(&sB[0][0]),  s2u(&sB[1][0])};
    uint32_t uPk[2] = {s2u(&sPk[0][0]), s2u(&sPk[1][0])};
    uint32_t uSc[2] = {s2u(&sScv[0][0]), s2u(&sScv[1][0])};

    const int mw = (wid >> 1) * 32, nw = (wid & 1) * 32;
    const int rowoff = (lane & 7) + ((lane >> 3) & 1) * 8;
    const int coloff = (lane >> 4) * 16;
    float acc[2][4][4] = {};

    auto CPL = [&](int kt, int s) {
        int k0 = kt * 32;  // halves
        cpa16(uA[s] + car * 80 + cab,      aG + k0 + (tid & 1) * 16);
        cpa16(uA[s] + car * 80 + cab + 16, aG + k0 + (tid & 1) * 16 + 8);
        cpa16(uPk[s] + (tid << 4), wp + (k0 >> 1) + q * 4);
        cpa4(uSc[s] + (tid << 2), scp + kt);
        CP_COMMIT();
    };
    auto DEQ = [&](int s) {
        int4 pk = *(const int4*)&sPk[s][tid << 2];
        unsigned sv = (unsigned)sScv[s][tid];
        __half2 hs = __float2half2_rn(__uint_as_float(sv << 23));
        __half2 h0 = __hmul2(lut[pk.x & 255], hs);
        __half2 h1 = __hmul2(lut[pk.y & 255], hs);
        __half2 h2 = __hmul2(lut[pk.z & 255], hs);
        __half2 h3 = __hmul2(lut[pk.w & 255], hs);
        *(uint4*)&sB[s][wr * 80 + q * 16] = make_uint4(
            *(unsigned*)&h0, *(unsigned*)&h1, *(unsigned*)&h2, *(unsigned*)&h3);
    };
    auto MMA = [&](int s) {
#pragma unroll
        for (int ks = 0; ks < 2; ks++) {
            int kb = ks * 32 + coloff;
            unsigned a[2][4], b[2][4];
#pragma unroll
            for (int mi = 0; mi < 2; mi++)
                ldsm_x4(a[mi][0], a[mi][1], a[mi][2], a[mi][3],
                        uA[s] + (mw + mi * 16 + rowoff) * 80 + kb);
#pragma unroll
            for (int p = 0; p < 2; p++)
                ldsm_x4(b[p][0], b[p][1], b[p][2], b[p][3],
                        uB[s] + (nw + p * 16 + rowoff) * 80 + kb);
#pragma unroll
            for (int mi = 0; mi < 2; mi++)
#pragma unroll
                for (int nj = 0; nj < 4; nj++) {
                    unsigned bf[2] = {b[nj >> 1][nj & 1], b[nj >> 1][(nj & 1) + 2]};
                    mma_f16(acc[mi][nj], a[mi], bf);
                }
        }
    };

    const int KT = I_ / 32;
    CPL(0, 0);
#pragma unroll 1
    for (int kt = 0; kt < KT; kt++) {
        int s = kt & 1;
        CP_WAIT0();
        DEQ(s);
        __syncthreads();
        if (kt + 1 < KT) CPL(kt + 1, s ^ 1);
        MMA(s);
    }

#pragma unroll
    for (int mi = 0; mi < 2; mi++) {
        int r = mw + mi * 16 + (lane >> 2);
#pragma unroll
        for (int nj = 0; nj < 4; nj++) {
            int col = n0 + nw + nj * 8 + 2 * (lane & 3);
            int row = m0 + r;
            if (row < cnt) {
                float wc = g_wt[e * T_ + row];
                *(float2*)&g_y[(e * T_ + row) * D_ + col] =
                    make_float2(acc[mi][nj][0] * wc, acc[mi][nj][1] * wc);
            }
            if (row + 8 < cnt) {
                float wc = g_wt[e * T_ + row + 8];
                *(float2*)&g_y[(e * T_ + row + 8) * D_ + col] =
                    make_float2(acc[mi][nj][2] * wc, acc[mi][nj][3] * wc);
            }
        }
    }
}

// ---------------- 5) combine -------------------------------------------------
__global__ __launch_bounds__(256) void k_combine(float* __restrict__ out) {
    int t = blockIdx.x;
    __shared__ int sl[E_];
    if (threadIdx.x < E_) sl[threadIdx.x] = g_slot[t * E_ + threadIdx.x];
    __syncthreads();
    for (int d = threadIdx.x; d < D_; d += 256) {
        float acc = 0.f;
#pragma unroll
        for (int e = 0; e < E_; e++) {
            int s = sl[e];
            if (s >= 0) acc += g_y[(e * T_ + s) * D_ + d];
        }
        out[t * D_ + d] = acc;
    }
}

// ---------------- launch -----------------------------------------------------
extern "C" void kernel_launch(void* const* d_in, const int* in_sizes, int n_in,
                              void* d_out, int out_size) {
    const float* x    = (const float*)d_in[0];
    const float* tw   = (const float*)d_in[1];
    const int*   tids = (const int*)d_in[2];
    const int*   w13  = (const int*)d_in[3];
    const int*   w13s = (const int*)d_in[4];
    const int*   w2   = (const int*)d_in[5];
    const int*   w2s  = (const int*)d_in[6];
    float* out = (float*)d_out;

    k_quant<<<(T_ * D_ / 32) / 8, 256>>>(x);
    k_route<<<1, 512>>>(tw, tids);
    k_gemm1<<<dim3(I_ / 32, T_ / 128, E_), 256>>>(w13, w13s);
    k_gemm2<<<dim3(D_ / 64, T_ / 128, E_), 256>>>(w2, w2s);
    k_combine<<<T_, 256>>>(out);
}